// round 7
// baseline (speedup 1.0000x reference)
#include <cuda_runtime.h>

#define HALF_DT 0.05f
#define A64f   0.09817477042f    /* 2*pi/64  */
#define A256f  0.02454369260f    /* 2*pi/256 */
#define A1024f 0.00613592315f    /* 2*pi/1024 */

__device__ float2 g_mult[1024];  // M(f)/1024 at p=16t+s, f=(t>>4)+4*(t&15)+64*rev2(s)

__device__ __forceinline__ float2 cadd(float2 a, float2 b){ return make_float2(a.x+b.x, a.y+b.y); }
__device__ __forceinline__ float2 csub(float2 a, float2 b){ return make_float2(a.x-b.x, a.y-b.y); }
__device__ __forceinline__ float2 cmul(float2 a, float2 b){
    return make_float2(fmaf(a.x, b.x, -a.y*b.y), fmaf(a.x, b.y, a.y*b.x));
}
__device__ __host__ __forceinline__ int rev2(int s){ return ((s & 3) << 2) | (s >> 2); }
__device__ __forceinline__ int sw16(int a){ return a ^ ((a >> 4) & 15); }

// ---------- pre-kernel: spectral Cayley multiplier in pipeline order ----------
__global__ void build_mult(const float* __restrict__ hw) {
    int p = blockIdx.x * blockDim.x + threadIdx.x;   // 0..1023
    if (p >= 1024) return;
    float w[15];
    #pragma unroll
    for (int k = 0; k < 15; k++) w[k] = hw[k];
    const int offs[11] = {1,2,3,4,5,6,8,10,12,16,20};
    float wm[11];
    wm[0]=w[0]; wm[1]=w[1]+w[5]; wm[2]=w[2]; wm[3]=w[3]+w[6]+w[10]; wm[4]=w[4];
    wm[5]=w[7]; wm[6]=w[8]+w[11]; wm[7]=w[9]; wm[8]=w[12]; wm[9]=w[13]; wm[10]=w[14];
    int t = p >> 4, s = p & 15;
    int f = (t >> 4) + 4 * (t & 15) + 64 * rev2(s);
    float lam = 0.0f;
    #pragma unroll
    for (int k = 0; k < 11; k++)
        lam += 2.0f * wm[k] * (1.0f - cospif((float)(offs[k] * f) * (1.0f/512.0f)));
    float sl  = HALF_DT * lam;
    float den = 1.0f + sl * sl;
    g_mult[p] = make_float2((1.0f - sl*sl) / (den * 1024.0f),
                            (-2.0f * sl)   / (den * 1024.0f));
}

// radix-4 butterfly: DFT4 (INV=false) / unnormalized IDFT4 (INV=true)
template<bool INV>
__device__ __forceinline__ void bf4(float2& A, float2& B, float2& C, float2& D){
    float2 t0 = cadd(A, C), t1 = csub(A, C);
    float2 t2 = cadd(B, D), t3 = csub(B, D);
    A = cadd(t0, t2); C = csub(t0, t2);
    if (!INV) {
        B = make_float2(t1.x + t3.y, t1.y - t3.x);
        D = make_float2(t1.x - t3.y, t1.y + t3.x);
    } else {
        B = make_float2(t1.x - t3.y, t1.y + t3.x);
        D = make_float2(t1.x + t3.y, t1.y - t3.x);
    }
}

// cos/sin(2*pi*k/16), k=0..9
__constant__ float C16c[10] = {1.f, 0.9238795325f, 0.7071067812f, 0.3826834324f,
    0.f, -0.3826834324f, -0.7071067812f, -0.9238795325f, -1.f, -0.9238795325f};
__constant__ float S16c[10] = {0.f, 0.3826834324f, 0.7071067812f, 0.9238795325f,
    1.f, 0.9238795325f, 0.7071067812f, 0.3826834324f, 0.f, -0.3826834324f};

// DFT16 DIF (INV=false) / unnorm IDFT16 DIF (INV=true): natural in, slot s -> digit rev2(s)
template<bool INV>
__device__ __forceinline__ void dft16(float2* r){
    #pragma unroll
    for (int j = 0; j < 4; j++) bf4<INV>(r[j], r[j+4], r[j+8], r[j+12]);
    #pragma unroll
    for (int j = 1; j < 4; j++){
        r[j+4]  = cmul(r[j+4],  make_float2(C16c[j],   INV ? S16c[j]   : -S16c[j]));
        r[j+8]  = cmul(r[j+8],  make_float2(C16c[2*j], INV ? S16c[2*j] : -S16c[2*j]));
        r[j+12] = cmul(r[j+12], make_float2(C16c[3*j], INV ? S16c[3*j] : -S16c[3*j]));
    }
    #pragma unroll
    for (int q = 0; q < 4; q++) bf4<INV>(r[4*q], r[4*q+1], r[4*q+2], r[4*q+3]);
}

// unnorm IDFT16 DIT: input slot s holds digit rev2(s), output natural
__device__ __forceinline__ void idit16(float2* r){
    #pragma unroll
    for (int q = 0; q < 4; q++) bf4<true>(r[4*q], r[4*q+1], r[4*q+2], r[4*q+3]);
    #pragma unroll
    for (int j = 1; j < 4; j++){
        r[j+4]  = cmul(r[j+4],  make_float2(C16c[j],   S16c[j]));
        r[j+8]  = cmul(r[j+8],  make_float2(C16c[2*j], S16c[2*j]));
        r[j+12] = cmul(r[j+12], make_float2(C16c[3*j], S16c[3*j]));
    }
    #pragma unroll
    for (int j = 0; j < 4; j++) bf4<true>(r[j], r[j+4], r[j+8], r[j+12]);
}

__global__ __launch_bounds__(64, 12)
void cayley_fft_kernel(const float* __restrict__ psi_r,
                       const float* __restrict__ psi_i,
                       const float* __restrict__ alpha,
                       float2* __restrict__ out) {
    __shared__ float2 sx[1024];
    __shared__ float  sred[2];

    const int t  = threadIdx.x;          // = tA + 16*tB
    const int tA = t & 15;               // n0
    const int tB = t >> 4;               // fwd phase1: n1 mod 4 ; later: f2
    const long long sys = blockIdx.x;
    const float* __restrict__ gr = psi_r + sys * 1024;
    const float* __restrict__ gi = psi_i + sys * 1024;

    // ---- load (slot s = u+4v holds element n = t + 64s), intensity ----
    float2 r[16];
    float isum = 0.0f;
    #pragma unroll
    for (int s = 0; s < 16; s++){
        int i = t + 64*s;
        r[s] = make_float2(gr[i], gi[i]);
        isum += r[s].x * r[s].x + r[s].y * r[s].y;
    }
    #pragma unroll
    for (int o = 16; o > 0; o >>= 1) isum += __shfl_xor_sync(0xffffffffu, isum, o);
    if ((t & 31) == 0) sred[t >> 5] = isum;
    __syncthreads();
    const float inv_mean = 1.0f / ((sred[0] + sred[1]) * (1.0f/1024.0f) + 1e-8f);

    // ---- nonlinear phase rotation ----
    #pragma unroll
    for (int s = 0; s < 16; s++){
        int i = t + 64*s;
        float inten = (r[s].x * r[s].x + r[s].y * r[s].y) * inv_mean;
        float ph = alpha[i] * inten;
        float sn, cs;
        __sincosf(ph, &sn, &cs);
        r[s] = make_float2(r[s].x * cs - r[s].y * sn, r[s].x * sn + r[s].y * cs);
    }

    // ==== fwd phase A: DFT4 over n2 (slot stride 4) + W64^{n1*f2} twiddle ====
    #pragma unroll
    for (int u = 0; u < 4; u++) bf4<false>(r[u], r[u+4], r[u+8], r[u+12]);
    {
        float sn, cs; __sincosf((float)tB * A64f, &sn, &cs);
        float2 b0 = make_float2(cs, -sn);
        #pragma unroll
        for (int u = 0; u < 4; u++){
            float2 b1 = cmul(b0, make_float2(C16c[u], -S16c[u]));   // W64^{tB+4u}
            float2 b2 = cmul(b1, b1), b3 = cmul(b2, b1);
            r[u+4]  = cmul(r[u+4],  b1);
            r[u+8]  = cmul(r[u+8],  b2);
            r[u+12] = cmul(r[u+12], b3);
        }
    }

    // ---- exchange 1: (u,v) -> all n1 per (n0, f2) ----
    __syncthreads();
    #pragma unroll
    for (int u = 0; u < 4; u++)
        #pragma unroll
        for (int v = 0; v < 4; v++)
            sx[sw16(tA + 64*tB + 16*v + 256*u)] = r[u + 4*v];
    __syncthreads();
    #pragma unroll
    for (int w = 0; w < 16; w++) r[w] = sx[sw16(tA + 16*tB + 64*w)];

    // ==== fwd phase B: DFT16 over n1 + W1024^{n0(f2+4f1)} twiddle ====
    dft16<false>(r);
    {
        float sn, cs;
        __sincosf((float)(tA * tB) * A1024f, &sn, &cs);
        float2 w = make_float2(cs, -sn);                 // W1024^{tA*tB}
        __sincosf((float)tA * A256f, &sn, &cs);
        float2 base = make_float2(cs, -sn);              // W256^{tA}
        #pragma unroll
        for (int f1 = 0; f1 < 16; f1++){
            r[rev2(f1)] = cmul(r[rev2(f1)], w);
            if (f1 < 15) w = cmul(w, base);
        }
    }

    // ---- exchange 2: -> all n0 per (f1, f2) ----
    __syncthreads();
    #pragma unroll
    for (int f1 = 0; f1 < 16; f1++)
        sx[sw16(tA + 256*tB + 16*f1)] = r[rev2(f1)];
    __syncthreads();
    #pragma unroll
    for (int w = 0; w < 16; w++) r[w] = sx[sw16(w + 16*tA + 256*tB)];

    // ==== fwd phase C: DFT16 over n0 -> slot s holds f0 = rev2(s) ====
    dft16<false>(r);

    // ==== spectral multiply ====
    {
        const float4* Mp = (const float4*)g_mult;
        #pragma unroll
        for (int c = 0; c < 8; c++){
            float4 m = Mp[8*t + c];
            r[2*c]   = cmul(r[2*c],   make_float2(m.x, m.y));
            r[2*c+1] = cmul(r[2*c+1], make_float2(m.z, m.w));
        }
    }

    // ==== inv phase C': IDFT16 over f0 (rev in -> natural n0 out) ====
    idit16(r);
    {   // conj twiddle W1024^{+n0*(f2+4f1)}
        float sn, cs; __sincosf((float)(tB + 4*tA) * A1024f, &sn, &cs);
        float2 base = make_float2(cs, sn), w = make_float2(1.0f, 0.0f);
        #pragma unroll
        for (int s = 0; s < 16; s++){
            if (s) r[s] = cmul(r[s], w);
            if (s < 15) w = cmul(w, base);
        }
    }

    // ---- exchange 3: -> all f1 per (n0, f2) ----
    __syncthreads();
    #pragma unroll
    for (int s = 0; s < 16; s++)
        sx[sw16(s + 16*tA + 256*tB)] = r[s];
    __syncthreads();
    #pragma unroll
    for (int w = 0; w < 16; w++) r[w] = sx[sw16(tA + 16*w + 256*tB)];

    // ==== inv phase B': IDFT16 over f1 (natural -> slot s holds n1=rev2(s)) ====
    dft16<true>(r);
    {   // conj twiddle W64^{+n1*f2}
        float sn, cs; __sincosf((float)tB * A64f, &sn, &cs);
        float2 base = make_float2(cs, sn), w = make_float2(1.0f, 0.0f);
        #pragma unroll
        for (int k = 0; k < 16; k++){
            if (k) r[rev2(k)] = cmul(r[rev2(k)], w);
            if (k < 15) w = cmul(w, base);
        }
    }

    // ---- exchange 4: -> (n0=tA, n1=tB+4u, f2=v) layout ----
    __syncthreads();
    #pragma unroll
    for (int k = 0; k < 16; k++)
        sx[sw16(tA + 16*tB + 64*k)] = r[rev2(k)];
    __syncthreads();
    #pragma unroll
    for (int u = 0; u < 4; u++)
        #pragma unroll
        for (int v = 0; v < 4; v++)
            r[u + 4*v] = sx[sw16(tA + 64*tB + 16*v + 256*u)];

    // ==== inv phase A': IDFT4 over f2 (all f2-twiddles already applied) ====
    #pragma unroll
    for (int u = 0; u < 4; u++) bf4<true>(r[u], r[u+4], r[u+8], r[u+12]);

    // ---- coalesced store: slot s = u+4v -> element t + 64s ----
    float2* __restrict__ o = out + sys * 1024;
    #pragma unroll
    for (int s = 0; s < 16; s++) o[t + 64*s] = r[s];
}

extern "C" void kernel_launch(void* const* d_in, const int* in_sizes, int n_in,
                              void* d_out, int out_size) {
    const float* psi_r = (const float*)d_in[0];
    const float* psi_i = (const float*)d_in[1];
    const float* alpha = (const float*)d_in[2];
    const float* ham_w = (const float*)d_in[3];
    float2* out = (float2*)d_out;

    const int nsys = in_sizes[0] / 1024;   // B*S = 16384

    build_mult<<<4, 256>>>(ham_w);
    cayley_fft_kernel<<<nsys, 64>>>(psi_r, psi_i, alpha, out);
}

// round 8
// speedup vs baseline: 1.1645x; 1.1645x over previous
#include <cuda_runtime.h>

#define HALF_DT 0.05f
#define A1024f 0.0061359231515f   /* 2*pi/1024 */

typedef unsigned long long u64;

__device__ float2 g_mult[1024];   // M(f)/1024 at table pos p = 32j + s2, f = j + 32*sig(s2)

// packed complex add: one add.rn.f32x2
__device__ __forceinline__ float2 cadd(float2 a, float2 b){
    float2 c;
    asm("add.rn.f32x2 %0, %1, %2;"
        : "=l"(reinterpret_cast<u64&>(c))
        : "l"(reinterpret_cast<const u64&>(a)), "l"(reinterpret_cast<const u64&>(b)));
    return c;
}
// packed complex sub: a - b = fma(b, {-1,-1}, a)
__device__ __forceinline__ float2 csub(float2 a, float2 b){
    float2 c;
    const u64 NEG1 = 0xBF800000BF800000ull;
    asm("fma.rn.f32x2 %0, %1, %2, %3;"
        : "=l"(reinterpret_cast<u64&>(c))
        : "l"(reinterpret_cast<const u64&>(b)), "l"(NEG1), "l"(reinterpret_cast<const u64&>(a)));
    return c;
}
__device__ __forceinline__ float2 cmul(float2 a, float2 b){
    return make_float2(fmaf(a.x, b.x, -a.y*b.y), fmaf(a.x, b.y, a.y*b.x));
}

// digit-reversal of the 4-2-4 mixed-radix length-32 FFT (involution)
__device__ __host__ __forceinline__ int sig(int s){ return ((s & 3) << 3) | (s & 4) | (s >> 3); }

// ---------- pre-kernel: spectral Cayley multiplier in pipeline order ----------
__global__ void build_mult(const float* __restrict__ hw) {
    int p = blockIdx.x * blockDim.x + threadIdx.x;   // 0..1023
    if (p >= 1024) return;
    float w[15];
    #pragma unroll
    for (int k = 0; k < 15; k++) w[k] = hw[k];
    const int offs[11] = {1,2,3,4,5,6,8,10,12,16,20};
    float wm[11];
    wm[0]=w[0]; wm[1]=w[1]+w[5]; wm[2]=w[2]; wm[3]=w[3]+w[6]+w[10]; wm[4]=w[4];
    wm[5]=w[7]; wm[6]=w[8]+w[11]; wm[7]=w[9]; wm[8]=w[12]; wm[9]=w[13]; wm[10]=w[14];
    int j  = p >> 5, s2 = p & 31;
    int f  = j + 32 * sig(s2);
    float lam = 0.0f;
    #pragma unroll
    for (int k = 0; k < 11; k++)
        lam += 2.0f * wm[k] * (1.0f - cospif((float)(offs[k] * f) * (1.0f/512.0f)));
    float sl  = HALF_DT * lam;
    float den = 1.0f + sl * sl;
    g_mult[p] = make_float2((1.0f - sl*sl) / (den * 1024.0f),
                            (-2.0f * sl)   / (den * 1024.0f));
}

// radix-4 butterfly: DFT4 (INV=false) / IDFT4 (INV=true)
template<bool INV>
__device__ __forceinline__ void bf4(float2& A, float2& B, float2& C, float2& D){
    float2 t0 = cadd(A, C), t1 = csub(A, C);
    float2 t2 = cadd(B, D), t3 = csub(B, D);
    A = cadd(t0, t2); C = csub(t0, t2);
    if (!INV) {
        B = make_float2(t1.x + t3.y, t1.y - t3.x);   // t1 - i t3
        D = make_float2(t1.x - t3.y, t1.y + t3.x);   // t1 + i t3
    } else {
        B = make_float2(t1.x - t3.y, t1.y + t3.x);
        D = make_float2(t1.x + t3.y, t1.y - t3.x);
    }
}

// in-register length-32 DFT/IDFT (DIF, radix 4-2-4), natural input,
// output slot s holds index sig(s). All twiddles compile-time constants.
template<bool INV>
__device__ __forceinline__ void fft32(float2* r){
    const float C32[8] = {1.0f, 0.98078528f, 0.92387953f, 0.83146961f,
                          0.70710678f, 0.55557023f, 0.38268343f, 0.19509032f};
    const float S32[8] = {0.0f, 0.19509032f, 0.38268343f, 0.55557023f,
                          0.70710678f, 0.83146961f, 0.92387953f, 0.98078528f};
    #pragma unroll
    for (int q = 0; q < 8; q++){
        bf4<INV>(r[q], r[q+8], r[q+16], r[q+24]);
        if (q){
            float2 W1 = make_float2(C32[q], INV ? S32[q] : -S32[q]);
            float2 W2 = cmul(W1, W1), W3 = cmul(W2, W1);
            r[q+8]  = cmul(r[q+8],  W1);
            r[q+16] = cmul(r[q+16], W2);
            r[q+24] = cmul(r[q+24], W3);
        }
    }
    const float SQ = 0.70710678118654752f;
    #pragma unroll
    for (int b = 0; b < 4; b++){
        float2* s = r + 8*b;
        #pragma unroll
        for (int q = 0; q < 4; q++){
            float2 d = csub(s[q], s[q+4]);
            s[q] = cadd(s[q], s[q+4]);
            s[q+4] = d;
        }
        if (!INV) {
            s[5] = cmul(s[5], make_float2(SQ, -SQ));
            s[6] = make_float2(s[6].y, -s[6].x);
            s[7] = cmul(s[7], make_float2(-SQ, -SQ));
        } else {
            s[5] = cmul(s[5], make_float2(SQ,  SQ));
            s[6] = make_float2(-s[6].y, s[6].x);
            s[7] = cmul(s[7], make_float2(-SQ,  SQ));
        }
    }
    #pragma unroll
    for (int c = 0; c < 8; c++) bf4<INV>(r[4*c], r[4*c+1], r[4*c+2], r[4*c+3]);
}

// apply r[sig(j)] *= base^j for j=1..31, 4-wide ILP (chain depth 8, not 31)
__device__ __forceinline__ void twiddle_chain(float2* r, float2 base){
    float2 b2 = cmul(base, base);
    float2 b3 = cmul(b2, base);
    float2 b4 = cmul(b2, b2);
    float2 bm[4] = {make_float2(1.0f, 0.0f), base, b2, b3};
    float2 p = make_float2(1.0f, 0.0f);
    #pragma unroll
    for (int k = 0; k < 8; k++){
        #pragma unroll
        for (int m = 0; m < 4; m++){
            int j = 4*k + m;
            if (j) r[sig(j)] = cmul(r[sig(j)], (k == 0) ? bm[m] : cmul(p, bm[m]));
        }
        if (k < 7) p = (k == 0) ? b4 : cmul(p, b4);
    }
}

__global__ __launch_bounds__(32, 16)
void cayley_fft_kernel(const float* __restrict__ psi_r,
                       const float* __restrict__ psi_i,
                       const float* __restrict__ alpha,
                       float2* __restrict__ out) {
    __shared__ float2 sx[1024];
    const int t = threadIdx.x;                 // 0..31
    const long long sys = blockIdx.x;
    const float* __restrict__ gr = psi_r + sys * 1024;
    const float* __restrict__ gi = psi_i + sys * 1024;

    // ---- load 32 elems (n = t + 32k, coalesced), intensity ----
    float2 r[32];
    float isum = 0.0f;
    #pragma unroll
    for (int k = 0; k < 32; k++){
        int i = t + 32*k;
        r[k] = make_float2(gr[i], gi[i]);
        isum += r[k].x * r[k].x + r[k].y * r[k].y;
    }
    #pragma unroll
    for (int o = 16; o > 0; o >>= 1) isum += __shfl_xor_sync(0xffffffffu, isum, o);
    const float inv_mean = 1.0f / (isum * (1.0f/1024.0f) + 1e-8f);

    // ---- nonlinear phase rotation ----
    #pragma unroll
    for (int k = 0; k < 32; k++){
        int i = t + 32*k;
        float inten = (r[k].x * r[k].x + r[k].y * r[k].y) * inv_mean;
        float ph = alpha[i] * inten;
        float s, c;
        __sincosf(ph, &s, &c);
        r[k] = make_float2(r[k].x * c - r[k].y * s, r[k].x * s + r[k].y * c);
    }

    // ---- phase 1: FFT32 over k; slot s holds j = sig(s) ----
    fft32<false>(r);

    // inter-phase twiddle W_1024^{t*j}
    float s0, c0;
    __sincosf((float)t * A1024f, &s0, &c0);
    twiddle_chain(r, make_float2(c0, -s0));

    // ---- exchange 1: (j,t) transpose, swizzled, warp-synchronous ----
    #pragma unroll
    for (int s = 0; s < 32; s++) sx[32*sig(s) + (t ^ sig(s))] = r[s];
    __syncwarp();
    #pragma unroll
    for (int e = 0; e < 32; e++) r[e] = sx[32*t + (e ^ t)];
    __syncwarp();   // buffer reused by exchange 2

    // ---- phase 2: FFT32 over t; slot s2 holds spectrum at f = j + 32*sig(s2) ----
    fft32<false>(r);

    // ---- spectral multiply (table in pipeline order, float4 loads) ----
    {
        const float4* Mp = (const float4*)g_mult;
        #pragma unroll
        for (int c = 0; c < 16; c++){
            float4 m = Mp[16*t + c];
            r[2*c]   = cmul(r[2*c],   make_float2(m.x, m.y));
            r[2*c+1] = cmul(r[2*c+1], make_float2(m.z, m.w));
        }
    }

    // ---- reorder slots to natural h order (sig is an involution: register swaps) ----
    #pragma unroll
    for (int d = 0; d < 2; d++)
        #pragma unroll
        for (int b = 0; b < 4; b++)
            #pragma unroll
            for (int e = b + 1; e < 4; e++){
                int i1 = 8*b + 4*d + e, i2 = 8*e + 4*d + b;
                float2 tmp = r[i1]; r[i1] = r[i2]; r[i2] = tmp;
            }

    // ---- phase 3: IFFT32 over h; slot s holds u at position sig(s) ----
    fft32<true>(r);

    // inter-phase twiddle W_1024^{-t*j} (conj base)
    twiddle_chain(r, make_float2(c0, s0));

    // ---- exchange 2: same addressing ----
    #pragma unroll
    for (int s = 0; s < 32; s++) sx[32*sig(s) + (t ^ sig(s))] = r[s];
    __syncwarp();
    #pragma unroll
    for (int e = 0; e < 32; e++) r[e] = sx[32*t + (e ^ t)];

    // ---- phase 4: IFFT32 over j; slot s holds x[t + 32*sig(s)] ----
    fft32<true>(r);

    // ---- coalesced store ----
    float2* __restrict__ o = out + sys * 1024;
    #pragma unroll
    for (int s = 0; s < 32; s++) o[t + 32*sig(s)] = r[s];
}

extern "C" void kernel_launch(void* const* d_in, const int* in_sizes, int n_in,
                              void* d_out, int out_size) {
    const float* psi_r = (const float*)d_in[0];
    const float* psi_i = (const float*)d_in[1];
    const float* alpha = (const float*)d_in[2];
    const float* ham_w = (const float*)d_in[3];
    float2* out = (float2*)d_out;

    const int nsys = in_sizes[0] / 1024;   // B*S = 16384

    build_mult<<<4, 256>>>(ham_w);
    cayley_fft_kernel<<<nsys, 32>>>(psi_r, psi_i, alpha, out);
}

// round 9
// speedup vs baseline: 1.3586x; 1.1667x over previous
#include <cuda_runtime.h>

#define HALF_DT 0.05f
#define A1024f 0.0061359231515f   /* 2*pi/1024 */

typedef unsigned long long u64;

// warp-coalesced multiplier table: g_mult4[c*32 + t] packs slots (2c, 2c+1) for thread t
__device__ float4 g_mult4[512];

// packed complex add: one add.rn.f32x2
__device__ __forceinline__ float2 cadd(float2 a, float2 b){
    float2 c;
    asm("add.rn.f32x2 %0, %1, %2;"
        : "=l"(reinterpret_cast<u64&>(c))
        : "l"(reinterpret_cast<const u64&>(a)), "l"(reinterpret_cast<const u64&>(b)));
    return c;
}
// packed complex sub: a - b = fma(b, {-1,-1}, a)
__device__ __forceinline__ float2 csub(float2 a, float2 b){
    float2 c;
    const u64 NEG1 = 0xBF800000BF800000ull;
    asm("fma.rn.f32x2 %0, %1, %2, %3;"
        : "=l"(reinterpret_cast<u64&>(c))
        : "l"(reinterpret_cast<const u64&>(b)), "l"(NEG1), "l"(reinterpret_cast<const u64&>(a)));
    return c;
}
__device__ __forceinline__ float2 cmul(float2 a, float2 b){
    return make_float2(fmaf(a.x, b.x, -a.y*b.y), fmaf(a.x, b.y, a.y*b.x));
}

// digit-reversal of the 4-2-4 mixed-radix length-32 FFT (involution)
__device__ __host__ __forceinline__ int sig(int s){ return ((s & 3) << 3) | (s & 4) | (s >> 3); }

// ---------- pre-kernel: spectral Cayley multiplier, coalesced layout ----------
__global__ void build_mult(const float* __restrict__ hw) {
    int q = blockIdx.x * blockDim.x + threadIdx.x;   // 0..1023
    if (q >= 1024) return;
    float w[15];
    #pragma unroll
    for (int k = 0; k < 15; k++) w[k] = hw[k];
    const int offs[11] = {1,2,3,4,5,6,8,10,12,16,20};
    float wm[11];
    wm[0]=w[0]; wm[1]=w[1]+w[5]; wm[2]=w[2]; wm[3]=w[3]+w[6]+w[10]; wm[4]=w[4];
    wm[5]=w[7]; wm[6]=w[8]+w[11]; wm[7]=w[9]; wm[8]=w[12]; wm[9]=w[13]; wm[10]=w[14];
    // q = 64c + 2t + h  ->  float2 index q of g_mult4 holds slot s=2c+h for thread t
    int c = q >> 6, t = (q >> 1) & 31, h = q & 1;
    int s = 2*c + h;
    int f = t + 32 * sig(s);
    float lam = 0.0f;
    #pragma unroll
    for (int k = 0; k < 11; k++)
        lam += 2.0f * wm[k] * (1.0f - cospif((float)(offs[k] * f) * (1.0f/512.0f)));
    float sl  = HALF_DT * lam;
    float den = 1.0f + sl * sl;
    ((float2*)g_mult4)[q] = make_float2((1.0f - sl*sl) / (den * 1024.0f),
                                        (-2.0f * sl)   / (den * 1024.0f));
}

// radix-4 butterfly: DFT4 (INV=false) / IDFT4 (INV=true)
template<bool INV>
__device__ __forceinline__ void bf4(float2& A, float2& B, float2& C, float2& D){
    float2 t0 = cadd(A, C), t1 = csub(A, C);
    float2 t2 = cadd(B, D), t3 = csub(B, D);
    A = cadd(t0, t2); C = csub(t0, t2);
    if (!INV) {
        B = make_float2(t1.x + t3.y, t1.y - t3.x);   // t1 - i t3
        D = make_float2(t1.x - t3.y, t1.y + t3.x);   // t1 + i t3
    } else {
        B = make_float2(t1.x - t3.y, t1.y + t3.x);
        D = make_float2(t1.x + t3.y, t1.y - t3.x);
    }
}

// in-register length-32 DFT/IDFT (DIF, radix 4-2-4), natural input,
// output slot s holds index sig(s). All twiddles compile-time constants.
template<bool INV>
__device__ __forceinline__ void fft32(float2* r){
    const float C32[8] = {1.0f, 0.98078528f, 0.92387953f, 0.83146961f,
                          0.70710678f, 0.55557023f, 0.38268343f, 0.19509032f};
    const float S32[8] = {0.0f, 0.19509032f, 0.38268343f, 0.55557023f,
                          0.70710678f, 0.83146961f, 0.92387953f, 0.98078528f};
    #pragma unroll
    for (int q = 0; q < 8; q++){
        bf4<INV>(r[q], r[q+8], r[q+16], r[q+24]);
        if (q){
            float2 W1 = make_float2(C32[q], INV ? S32[q] : -S32[q]);
            float2 W2 = cmul(W1, W1), W3 = cmul(W2, W1);
            r[q+8]  = cmul(r[q+8],  W1);
            r[q+16] = cmul(r[q+16], W2);
            r[q+24] = cmul(r[q+24], W3);
        }
    }
    const float SQ = 0.70710678118654752f;
    #pragma unroll
    for (int b = 0; b < 4; b++){
        float2* s = r + 8*b;
        #pragma unroll
        for (int q = 0; q < 4; q++){
            float2 d = csub(s[q], s[q+4]);
            s[q] = cadd(s[q], s[q+4]);
            s[q+4] = d;
        }
        if (!INV) {
            s[5] = cmul(s[5], make_float2(SQ, -SQ));
            s[6] = make_float2(s[6].y, -s[6].x);
            s[7] = cmul(s[7], make_float2(-SQ, -SQ));
        } else {
            s[5] = cmul(s[5], make_float2(SQ,  SQ));
            s[6] = make_float2(-s[6].y, s[6].x);
            s[7] = cmul(s[7], make_float2(-SQ,  SQ));
        }
    }
    #pragma unroll
    for (int c = 0; c < 8; c++) bf4<INV>(r[4*c], r[4*c+1], r[4*c+2], r[4*c+3]);
}

// apply r[sig(j)] *= base^j for j=1..31, 4-wide ILP (chain depth 8, not 31)
__device__ __forceinline__ void twiddle_chain(float2* r, float2 base){
    float2 b2 = cmul(base, base);
    float2 b3 = cmul(b2, base);
    float2 b4 = cmul(b2, b2);
    float2 bm[4] = {make_float2(1.0f, 0.0f), base, b2, b3};
    float2 p = make_float2(1.0f, 0.0f);
    #pragma unroll
    for (int k = 0; k < 8; k++){
        #pragma unroll
        for (int m = 0; m < 4; m++){
            int j = 4*k + m;
            if (j) r[sig(j)] = cmul(r[sig(j)], (k == 0) ? bm[m] : cmul(p, bm[m]));
        }
        if (k < 7) p = (k == 0) ? b4 : cmul(p, b4);
    }
}

__global__ __launch_bounds__(32, 16)
void cayley_fft_kernel(const float* __restrict__ psi_r,
                       const float* __restrict__ psi_i,
                       const float* __restrict__ alpha,
                       float2* __restrict__ out) {
    __shared__ float2 sx[1024];
    const int t = threadIdx.x;                 // 0..31
    const long long sys = blockIdx.x;
    const float* __restrict__ gr = psi_r + sys * 1024;
    const float* __restrict__ gi = psi_i + sys * 1024;

    // ---- load 32 elems (n = t + 32k, coalesced), intensity ----
    float2 r[32];
    float isum = 0.0f;
    #pragma unroll
    for (int k = 0; k < 32; k++){
        int i = t + 32*k;
        r[k] = make_float2(gr[i], gi[i]);
        isum += r[k].x * r[k].x + r[k].y * r[k].y;
    }
    #pragma unroll
    for (int o = 16; o > 0; o >>= 1) isum += __shfl_xor_sync(0xffffffffu, isum, o);
    const float inv_mean = 1.0f / (isum * (1.0f/1024.0f) + 1e-8f);

    // ---- nonlinear phase rotation ----
    #pragma unroll
    for (int k = 0; k < 32; k++){
        int i = t + 32*k;
        float inten = (r[k].x * r[k].x + r[k].y * r[k].y) * inv_mean;
        float ph = alpha[i] * inten;
        float s, c;
        __sincosf(ph, &s, &c);
        r[k] = make_float2(r[k].x * c - r[k].y * s, r[k].x * s + r[k].y * c);
    }

    // ---- phase 1: FFT32 over k; slot s holds j = sig(s) ----
    fft32<false>(r);

    // inter-phase twiddle W_1024^{t*j}
    float s0, c0;
    __sincosf((float)t * A1024f, &s0, &c0);
    twiddle_chain(r, make_float2(c0, -s0));

    // ---- exchange 1: (j,t) transpose, swizzled, warp-synchronous ----
    #pragma unroll
    for (int s = 0; s < 32; s++) sx[32*sig(s) + (t ^ sig(s))] = r[s];
    __syncwarp();
    #pragma unroll
    for (int e = 0; e < 32; e++) r[e] = sx[32*t + (e ^ t)];
    __syncwarp();   // buffer reused by exchange 2

    // ---- phase 2: FFT32 over t; slot s2 holds spectrum at f = j + 32*sig(s2) ----
    fft32<false>(r);

    // ---- spectral multiply: warp-coalesced float4 table loads ----
    {
        const float4* __restrict__ Mp = g_mult4;
        #pragma unroll
        for (int c = 0; c < 16; c++){
            float4 m = Mp[c*32 + t];
            r[2*c]   = cmul(r[2*c],   make_float2(m.x, m.y));
            r[2*c+1] = cmul(r[2*c+1], make_float2(m.z, m.w));
        }
    }

    // ---- reorder slots to natural h order (sig is an involution: register swaps) ----
    #pragma unroll
    for (int d = 0; d < 2; d++)
        #pragma unroll
        for (int b = 0; b < 4; b++)
            #pragma unroll
            for (int e = b + 1; e < 4; e++){
                int i1 = 8*b + 4*d + e, i2 = 8*e + 4*d + b;
                float2 tmp = r[i1]; r[i1] = r[i2]; r[i2] = tmp;
            }

    // ---- phase 3: IFFT32 over h; slot s holds u at position sig(s) ----
    fft32<true>(r);

    // inter-phase twiddle W_1024^{-t*j} (conj base)
    twiddle_chain(r, make_float2(c0, s0));

    // ---- exchange 2: same addressing ----
    #pragma unroll
    for (int s = 0; s < 32; s++) sx[32*sig(s) + (t ^ sig(s))] = r[s];
    __syncwarp();
    #pragma unroll
    for (int e = 0; e < 32; e++) r[e] = sx[32*t + (e ^ t)];

    // ---- phase 4: IFFT32 over j; slot s holds x[t + 32*sig(s)] ----
    fft32<true>(r);

    // ---- coalesced store ----
    float2* __restrict__ o = out + sys * 1024;
    #pragma unroll
    for (int s = 0; s < 32; s++) o[t + 32*sig(s)] = r[s];
}

extern "C" void kernel_launch(void* const* d_in, const int* in_sizes, int n_in,
                              void* d_out, int out_size) {
    const float* psi_r = (const float*)d_in[0];
    const float* psi_i = (const float*)d_in[1];
    const float* alpha = (const float*)d_in[2];
    const float* ham_w = (const float*)d_in[3];
    float2* out = (float2*)d_out;

    const int nsys = in_sizes[0] / 1024;   // B*S = 16384

    build_mult<<<4, 256>>>(ham_w);
    cayley_fft_kernel<<<nsys, 32>>>(psi_r, psi_i, alpha, out);
}

// round 10
// speedup vs baseline: 1.3655x; 1.0051x over previous
#include <cuda_runtime.h>

#define HALF_DT 0.05f
#define A1024f 0.0061359231515f   /* 2*pi/1024 */

typedef unsigned long long u64;

// warp-coalesced multiplier table: g_mult4[c*32 + t] packs slots (2c, 2c+1) for thread t
__device__ float4 g_mult4[512];

// packed complex add: one add.rn.f32x2
__device__ __forceinline__ float2 cadd(float2 a, float2 b){
    float2 c;
    asm("add.rn.f32x2 %0, %1, %2;"
        : "=l"(reinterpret_cast<u64&>(c))
        : "l"(reinterpret_cast<const u64&>(a)), "l"(reinterpret_cast<const u64&>(b)));
    return c;
}
// packed complex sub: a - b = fma(b, {-1,-1}, a)
__device__ __forceinline__ float2 csub(float2 a, float2 b){
    float2 c;
    const u64 NEG1 = 0xBF800000BF800000ull;
    asm("fma.rn.f32x2 %0, %1, %2, %3;"
        : "=l"(reinterpret_cast<u64&>(c))
        : "l"(reinterpret_cast<const u64&>(b)), "l"(NEG1), "l"(reinterpret_cast<const u64&>(a)));
    return c;
}
__device__ __forceinline__ float2 cmul(float2 a, float2 b){
    return make_float2(fmaf(a.x, b.x, -a.y*b.y), fmaf(a.x, b.y, a.y*b.x));
}

// digit-reversal of the 4-2-4 mixed-radix length-32 FFT (involution)
__device__ __host__ __forceinline__ int sig(int s){ return ((s & 3) << 3) | (s & 4) | (s >> 3); }

// ---------- pre-kernel: spectral Cayley multiplier, coalesced layout ----------
__global__ void build_mult(const float* __restrict__ hw) {
    int q = blockIdx.x * blockDim.x + threadIdx.x;   // 0..1023
    if (q >= 1024) return;
    float w[15];
    #pragma unroll
    for (int k = 0; k < 15; k++) w[k] = hw[k];
    const int offs[11] = {1,2,3,4,5,6,8,10,12,16,20};
    float wm[11];
    wm[0]=w[0]; wm[1]=w[1]+w[5]; wm[2]=w[2]; wm[3]=w[3]+w[6]+w[10]; wm[4]=w[4];
    wm[5]=w[7]; wm[6]=w[8]+w[11]; wm[7]=w[9]; wm[8]=w[12]; wm[9]=w[13]; wm[10]=w[14];
    // q = 64c + 2t + h  ->  float2 index q of g_mult4 holds slot s=2c+h for thread t
    int c = q >> 6, t = (q >> 1) & 31, h = q & 1;
    int s = 2*c + h;
    int f = t + 32 * sig(s);
    float lam = 0.0f;
    #pragma unroll
    for (int k = 0; k < 11; k++)
        lam += 2.0f * wm[k] * (1.0f - cospif((float)(offs[k] * f) * (1.0f/512.0f)));
    float sl  = HALF_DT * lam;
    float den = 1.0f + sl * sl;
    ((float2*)g_mult4)[q] = make_float2((1.0f - sl*sl) / (den * 1024.0f),
                                        (-2.0f * sl)   / (den * 1024.0f));
}

// radix-4 butterfly: DFT4 (INV=false) / IDFT4 (INV=true)
template<bool INV>
__device__ __forceinline__ void bf4(float2& A, float2& B, float2& C, float2& D){
    float2 t0 = cadd(A, C), t1 = csub(A, C);
    float2 t2 = cadd(B, D), t3 = csub(B, D);
    A = cadd(t0, t2); C = csub(t0, t2);
    if (!INV) {
        B = make_float2(t1.x + t3.y, t1.y - t3.x);   // t1 - i t3
        D = make_float2(t1.x - t3.y, t1.y + t3.x);   // t1 + i t3
    } else {
        B = make_float2(t1.x - t3.y, t1.y + t3.x);
        D = make_float2(t1.x + t3.y, t1.y - t3.x);
    }
}

// in-register length-32 DFT/IDFT (DIF, radix 4-2-4), natural input,
// output slot s holds index sig(s). All twiddles compile-time constants.
template<bool INV>
__device__ __forceinline__ void fft32(float2* r){
    const float C32[8] = {1.0f, 0.98078528f, 0.92387953f, 0.83146961f,
                          0.70710678f, 0.55557023f, 0.38268343f, 0.19509032f};
    const float S32[8] = {0.0f, 0.19509032f, 0.38268343f, 0.55557023f,
                          0.70710678f, 0.83146961f, 0.92387953f, 0.98078528f};
    #pragma unroll
    for (int q = 0; q < 8; q++){
        bf4<INV>(r[q], r[q+8], r[q+16], r[q+24]);
        if (q){
            float2 W1 = make_float2(C32[q], INV ? S32[q] : -S32[q]);
            float2 W2 = cmul(W1, W1), W3 = cmul(W2, W1);
            r[q+8]  = cmul(r[q+8],  W1);
            r[q+16] = cmul(r[q+16], W2);
            r[q+24] = cmul(r[q+24], W3);
        }
    }
    const float SQ = 0.70710678118654752f;
    #pragma unroll
    for (int b = 0; b < 4; b++){
        float2* s = r + 8*b;
        #pragma unroll
        for (int q = 0; q < 4; q++){
            float2 d = csub(s[q], s[q+4]);
            s[q] = cadd(s[q], s[q+4]);
            s[q+4] = d;
        }
        if (!INV) {
            s[5] = cmul(s[5], make_float2(SQ, -SQ));
            s[6] = make_float2(s[6].y, -s[6].x);
            s[7] = cmul(s[7], make_float2(-SQ, -SQ));
        } else {
            s[5] = cmul(s[5], make_float2(SQ,  SQ));
            s[6] = make_float2(-s[6].y, s[6].x);
            s[7] = cmul(s[7], make_float2(-SQ,  SQ));
        }
    }
    #pragma unroll
    for (int c = 0; c < 8; c++) bf4<INV>(r[4*c], r[4*c+1], r[4*c+2], r[4*c+3]);
}

// apply r[sig(j)] *= base^j for j=1..31, 4-wide ILP (chain depth 8, not 31)
__device__ __forceinline__ void twiddle_chain(float2* r, float2 base){
    float2 b2 = cmul(base, base);
    float2 b3 = cmul(b2, base);
    float2 b4 = cmul(b2, b2);
    float2 bm[4] = {make_float2(1.0f, 0.0f), base, b2, b3};
    float2 p = make_float2(1.0f, 0.0f);
    #pragma unroll
    for (int k = 0; k < 8; k++){
        #pragma unroll
        for (int m = 0; m < 4; m++){
            int j = 4*k + m;
            if (j) r[sig(j)] = cmul(r[sig(j)], (k == 0) ? bm[m] : cmul(p, bm[m]));
        }
        if (k < 7) p = (k == 0) ? b4 : cmul(p, b4);
    }
}

__global__ __launch_bounds__(32, 20)
void cayley_fft_kernel(const float* __restrict__ psi_r,
                       const float* __restrict__ psi_i,
                       const float* __restrict__ alpha,
                       float2* __restrict__ out) {
    // padded layout: row stride 33 float2 -> all exchange addresses are
    // [base_reg + compile-time-imm], bank-conflict-free in every 16-lane phase
    __shared__ float2 sx[33 * 32];
    const int t = threadIdx.x;                 // 0..31
    const long long sys = blockIdx.x;
    const float* __restrict__ gr = psi_r + sys * 1024;
    const float* __restrict__ gi = psi_i + sys * 1024;

    // ---- load 32 elems (n = t + 32k, coalesced), intensity ----
    float2 r[32];
    float isum = 0.0f;
    #pragma unroll
    for (int k = 0; k < 32; k++){
        int i = t + 32*k;
        r[k] = make_float2(gr[i], gi[i]);
        isum += r[k].x * r[k].x + r[k].y * r[k].y;
    }
    #pragma unroll
    for (int o = 16; o > 0; o >>= 1) isum += __shfl_xor_sync(0xffffffffu, isum, o);
    const float inv_mean = 1.0f / (isum * (1.0f/1024.0f) + 1e-8f);

    // ---- nonlinear phase rotation ----
    #pragma unroll
    for (int k = 0; k < 32; k++){
        int i = t + 32*k;
        float inten = (r[k].x * r[k].x + r[k].y * r[k].y) * inv_mean;
        float ph = alpha[i] * inten;
        float s, c;
        __sincosf(ph, &s, &c);
        r[k] = make_float2(r[k].x * c - r[k].y * s, r[k].x * s + r[k].y * c);
    }

    // ---- phase 1: FFT32 over k; slot s holds j = sig(s) ----
    fft32<false>(r);

    // inter-phase twiddle W_1024^{t*j}
    float s0, c0;
    __sincosf((float)t * A1024f, &s0, &c0);
    twiddle_chain(r, make_float2(c0, -s0));

    // ---- exchange 1: (j,t) transpose, padded stride, warp-synchronous ----
    {
        float2* __restrict__ st = sx + t;        // store: row sig(s), col t
        #pragma unroll
        for (int s = 0; s < 32; s++) st[33 * sig(s)] = r[s];
    }
    __syncwarp();
    {
        const float2* __restrict__ ld = sx + 33 * t;   // load: row t, col e
        #pragma unroll
        for (int e = 0; e < 32; e++) r[e] = ld[e];
    }
    __syncwarp();   // buffer reused by exchange 2

    // ---- phase 2: FFT32 over t; slot s2 holds spectrum at f = j + 32*sig(s2) ----
    fft32<false>(r);

    // ---- spectral multiply: warp-coalesced float4 table loads ----
    {
        const float4* __restrict__ Mp = g_mult4;
        #pragma unroll
        for (int c = 0; c < 16; c++){
            float4 m = Mp[c*32 + t];
            r[2*c]   = cmul(r[2*c],   make_float2(m.x, m.y));
            r[2*c+1] = cmul(r[2*c+1], make_float2(m.z, m.w));
        }
    }

    // ---- reorder slots to natural h order (sig is an involution: register swaps) ----
    #pragma unroll
    for (int d = 0; d < 2; d++)
        #pragma unroll
        for (int b = 0; b < 4; b++)
            #pragma unroll
            for (int e = b + 1; e < 4; e++){
                int i1 = 8*b + 4*d + e, i2 = 8*e + 4*d + b;
                float2 tmp = r[i1]; r[i1] = r[i2]; r[i2] = tmp;
            }

    // ---- phase 3: IFFT32 over h; slot s holds u at position sig(s) ----
    fft32<true>(r);

    // inter-phase twiddle W_1024^{-t*j} (conj base)
    twiddle_chain(r, make_float2(c0, s0));

    // ---- exchange 2: same addressing ----
    {
        float2* __restrict__ st = sx + t;
        #pragma unroll
        for (int s = 0; s < 32; s++) st[33 * sig(s)] = r[s];
    }
    __syncwarp();
    {
        const float2* __restrict__ ld = sx + 33 * t;
        #pragma unroll
        for (int e = 0; e < 32; e++) r[e] = ld[e];
    }

    // ---- phase 4: IFFT32 over j; slot s holds x[t + 32*sig(s)] ----
    fft32<true>(r);

    // ---- coalesced store (per-s: warp writes one contiguous 256B line pair) ----
    float2* __restrict__ o = out + sys * 1024 + t;
    #pragma unroll
    for (int s = 0; s < 32; s++) o[32 * sig(s)] = r[s];
}

extern "C" void kernel_launch(void* const* d_in, const int* in_sizes, int n_in,
                              void* d_out, int out_size) {
    const float* psi_r = (const float*)d_in[0];
    const float* psi_i = (const float*)d_in[1];
    const float* alpha = (const float*)d_in[2];
    const float* ham_w = (const float*)d_in[3];
    float2* out = (float2*)d_out;

    const int nsys = in_sizes[0] / 1024;   // B*S = 16384

    build_mult<<<4, 256>>>(ham_w);
    cayley_fft_kernel<<<nsys, 32>>>(psi_r, psi_i, alpha, out);
}